// round 6
// baseline (speedup 1.0000x reference)
#include <cuda_runtime.h>

// Problem constants
#define BSZ   4096
#define DD    256
#define NIDS  100000
#define MARGIN 0.5f

// GEMM tiling
#define BM 128
#define BN 128
#define BK 16
#define NT (DD / BK)     // 16 k-tiles
#define PAD 4            // smem row padding: 132-float stride (33x16B) breaks STS conflicts

// Scratch (no cudaMalloc allowed)
__device__ unsigned long long g_min[BSZ];   // packed (fkey(simval)<<32 | col)
__device__ float              g_loss[BSZ];
__device__ int                g_label[BSZ]; // dtype-normalized labels

// Monotone increasing float -> uint mapping (smaller float => smaller key)
__device__ __forceinline__ unsigned int fkey(float x) {
    unsigned int u = __float_as_uint(x);
    return (u & 0x80000000u) ? ~u : (u | 0x80000000u);
}

// ---------------------------------------------------------------------------
// Prologue: detect label dtype (int32 vs little-endian int64), normalize to
// g_label[], and init g_min[]. Reads only the first BSZ*4 bytes of the label
// buffer in the int32 case (in-bounds for both layouts).
// If int64: odd 32-bit words (high halves) of small non-negative values are 0.
// If int32: 32 consecutive odd-index labels all being 0 has prob ~1e-160.
// ---------------------------------------------------------------------------
__global__ void prologue_kernel(const int* __restrict__ lab32) {
    __shared__ int is64;
    if (threadIdx.x == 0) {
        int odd_or = 0;
        #pragma unroll
        for (int i = 0; i < 32; i++) odd_or |= lab32[2 * i + 1];
        is64 = (odd_or == 0) ? 1 : 0;
    }
    __syncthreads();
    const int i = blockIdx.x * blockDim.x + threadIdx.x;
    if (i < BSZ) {
        g_label[i] = is64 ? lab32[2 * i] : lab32[i];
        g_min[i]   = 0xFFFFFFFFFFFFFFFFull;
    }
}

// ---------------------------------------------------------------------------
// Fused sim = ftr @ ftr^T tile + per-row masked argmin.
// Block: 256 threads, computes a 128x128 tile of sim, 8x8 per thread.
// ---------------------------------------------------------------------------
__global__ __launch_bounds__(256)
void sim_argmin_kernel(const float* __restrict__ ftr) {
    __shared__ __align__(16) float As[2][BK][BM + PAD];
    __shared__ __align__(16) float Bs[2][BK][BN + PAD];
    __shared__ unsigned long long rowMin[BM];
    __shared__ int slab[BM];

    const int tid  = threadIdx.x;
    const int tx   = tid & 15;        // 16 thread-cols
    const int ty   = tid >> 4;        // 16 thread-rows
    const int row0 = blockIdx.y * BM;
    const int col0 = blockIdx.x * BN;

    if (tid < BM) {
        rowMin[tid] = 0xFFFFFFFFFFFFFFFFull;
        slab[tid]   = g_label[row0 + tid];
    }

    float acc[8][8];
    #pragma unroll
    for (int i = 0; i < 8; i++)
        #pragma unroll
        for (int j = 0; j < 8; j++)
            acc[i][j] = 0.0f;

    // ---- preload k-tile 0 ----
    {
        #pragma unroll
        for (int l = 0; l < 2; l++) {
            int f = tid + l * 256;          // 512 float4 per operand tile
            int r = f >> 2;                 // row within tile (coalesced LDG)
            int kq = f & 3;                 // k-quad
            float4 va = *(const float4*)(ftr + (size_t)(row0 + r) * DD + kq * 4);
            float4 vb = *(const float4*)(ftr + (size_t)(col0 + r) * DD + kq * 4);
            As[0][kq * 4 + 0][r] = va.x; As[0][kq * 4 + 1][r] = va.y;
            As[0][kq * 4 + 2][r] = va.z; As[0][kq * 4 + 3][r] = va.w;
            Bs[0][kq * 4 + 0][r] = vb.x; Bs[0][kq * 4 + 1][r] = vb.y;
            Bs[0][kq * 4 + 2][r] = vb.z; Bs[0][kq * 4 + 3][r] = vb.w;
        }
    }
    __syncthreads();

    // ---- main loop over k-tiles, double buffered ----
    for (int kt = 0; kt < NT; kt++) {
        const int cur = kt & 1;
        float4 va[2], vb[2];
        const bool more = (kt + 1) < NT;

        if (more) {
            const int k0 = (kt + 1) * BK;
            #pragma unroll
            for (int l = 0; l < 2; l++) {
                int f = tid + l * 256;
                int r = f >> 2, kq = f & 3;
                va[l] = *(const float4*)(ftr + (size_t)(row0 + r) * DD + k0 + kq * 4);
                vb[l] = *(const float4*)(ftr + (size_t)(col0 + r) * DD + k0 + kq * 4);
            }
        }

        #pragma unroll
        for (int k = 0; k < BK; k++) {
            float a[8], b[8];
            *(float4*)&a[0] = *(const float4*)&As[cur][k][ty * 8 + 0];
            *(float4*)&a[4] = *(const float4*)&As[cur][k][ty * 8 + 4];
            *(float4*)&b[0] = *(const float4*)&Bs[cur][k][tx * 8 + 0];
            *(float4*)&b[4] = *(const float4*)&Bs[cur][k][tx * 8 + 4];
            #pragma unroll
            for (int i = 0; i < 8; i++)
                #pragma unroll
                for (int j = 0; j < 8; j++)
                    acc[i][j] = fmaf(a[i], b[j], acc[i][j]);
        }

        if (more) {
            const int nb = cur ^ 1;
            #pragma unroll
            for (int l = 0; l < 2; l++) {
                int f = tid + l * 256;
                int r = f >> 2, kq = f & 3;
                As[nb][kq * 4 + 0][r] = va[l].x; As[nb][kq * 4 + 1][r] = va[l].y;
                As[nb][kq * 4 + 2][r] = va[l].z; As[nb][kq * 4 + 3][r] = va[l].w;
                Bs[nb][kq * 4 + 0][r] = vb[l].x; Bs[nb][kq * 4 + 1][r] = vb[l].y;
                Bs[nb][kq * 4 + 2][r] = vb[l].z; Bs[nb][kq * 4 + 3][r] = vb[l].w;
            }
        }
        __syncthreads();
    }

    // ---- epilogue: masked argmin over this tile's columns ----
    #pragma unroll
    for (int i = 0; i < 8; i++) {
        const int gi  = ty * 8 + i;
        const int lab = slab[gi];
        unsigned long long best = 0xFFFFFFFFFFFFFFFFull;
        #pragma unroll
        for (int j = 0; j < 8; j++) {
            const int gj = col0 + tx * 8 + j;
            if (gj != lab) {   // reference masks column == label[row] with +inf
                unsigned long long p =
                    ((unsigned long long)fkey(acc[i][j]) << 32) | (unsigned int)gj;
                best = (p < best) ? p : best;
            }
        }
        atomicMin(&rowMin[gi], best);
    }
    __syncthreads();
    if (tid < BM) atomicMin(&g_min[row0 + tid], rowMin[tid]);
}

// ---------------------------------------------------------------------------
// Per-row loss: one warp per row.
// ---------------------------------------------------------------------------
__global__ __launch_bounds__(256)
void loss_kernel(const float* __restrict__ ftr,
                 const float* __restrict__ prototypes) {
    const int warp = (blockIdx.x * blockDim.x + threadIdx.x) >> 5;
    const int lane = threadIdx.x & 31;
    if (warp >= BSZ) return;
    const int r = warp;

    const int lab = g_label[r];
    const int ni  = (int)(g_min[r] & 0xFFFFFFFFull);

    const float* x  = ftr + (size_t)r * DD;
    const float* y  = prototypes + (size_t)lab * DD;
    const float* nv = ftr + (size_t)ni * DD;

    float pd = 0.0f, nd = 0.0f;
    #pragma unroll
    for (int t = 0; t < DD / 32; t++) {
        const int c = lane + t * 32;
        const float xv = x[c];
        const float dy = xv - y[c];
        const float dn = xv - nv[c];
        pd = fmaf(dy, dy, pd);
        nd = fmaf(dn, dn, nd);
    }
    #pragma unroll
    for (int o = 16; o > 0; o >>= 1) {
        pd += __shfl_down_sync(0xFFFFFFFFu, pd, o);
        nd += __shfl_down_sync(0xFFFFFFFFu, nd, o);
    }
    if (lane == 0) g_loss[r] = fmaxf(pd - nd + MARGIN, 0.0f);
}

// ---------------------------------------------------------------------------
// Deterministic single-block mean reduction.
// ---------------------------------------------------------------------------
__global__ void reduce_kernel(float* __restrict__ out) {
    __shared__ float s[1024];
    const int t = threadIdx.x;
    float v = g_loss[t] + g_loss[t + 1024] + g_loss[t + 2048] + g_loss[t + 3072];
    s[t] = v;
    __syncthreads();
    #pragma unroll
    for (int o = 512; o > 0; o >>= 1) {
        if (t < o) s[t] += s[t + o];
        __syncthreads();
    }
    if (t == 0) out[0] = s[0] / (float)BSZ;
}

extern "C" void kernel_launch(void* const* d_in, const int* in_sizes, int n_in,
                              void* d_out, int out_size) {
    const float* ftr        = (const float*)d_in[0];
    // d_in[1] = teachor_ftr : unused by the reference computation
    const float* prototypes = (const float*)d_in[2];
    const int*   label_raw  = (const int*)d_in[3];   // int32 or int64 — sniffed on device
    float*       out        = (float*)d_out;

    prologue_kernel<<<BSZ / 256, 256>>>(label_raw);

    dim3 grid(BSZ / BN, BSZ / BM);   // 32 x 32 = 1024 blocks
    sim_argmin_kernel<<<grid, 256>>>(ftr);

    loss_kernel<<<(BSZ * 32) / 256, 256>>>(ftr, prototypes);

    reduce_kernel<<<1, 1024>>>(out);
}